// round 1
// baseline (speedup 1.0000x reference)
#include <cuda_runtime.h>

#define B_   16
#define C_   384
#define H_   56
#define W_   56
#define HW_  3136
#define NHW_ 50176
#define TOT_ 19267584
#define KL   31
#define PL   15
#define KS   5
#define TS   86      // 56 + 2*15
#define STR  88      // smem row stride: 8*dr != 7*ds (mod 32) -> conflict-free

// Scratch (allocation-free contract: __device__ globals)
__device__ float g_yl[TOT_];
__device__ float g_ys[TOT_];
__device__ float g_acc[C_ * 4];   // per channel: sumL, sqL, sumS, sqS
__device__ float g_prm[C_ * 3];   // per channel: aL, aS, bias

__global__ void k_zero() {
    int i = blockIdx.x * blockDim.x + threadIdx.x;
    if (i < C_ * 4) g_acc[i] = 0.f;
}

__global__ __launch_bounds__(256) void k_conv(const float* __restrict__ x,
                                              const float* __restrict__ wl_g,
                                              const float* __restrict__ ws_g) {
    __shared__ float tile[TS * STR];
    __shared__ float wl[KL * KL];
    __shared__ float ws[KS * KS];
    __shared__ float red[8 * 4];

    const int blk = blockIdx.x;          // n*C + c
    const int c   = blk % C_;
    const int tid = threadIdx.x;
    const float* img = x + (size_t)blk * HW_;

    // Load padded tile (zero halo of 15)
    for (int idx = tid; idx < TS * TS; idx += 256) {
        int r = idx / TS, q = idx - r * TS;
        int hy = r - PL, wx = q - PL;
        float v = 0.f;
        if (hy >= 0 && hy < H_ && wx >= 0 && wx < W_) v = img[hy * W_ + wx];
        tile[r * STR + q] = v;
    }
    for (int idx = tid; idx < KL * KL; idx += 256) wl[idx] = wl_g[c * KL * KL + idx];
    if (tid < KS * KS) ws[tid] = ws_g[c * KS * KS + tid];
    __syncthreads();

    float sL = 0.f, qL = 0.f, sS = 0.f, qS = 0.f;
    const int strip = tid & 7;
    const int col0  = strip * 7;

    #pragma unroll 1
    for (int rr = 0; rr < 2; rr++) {
        const int h = (tid >> 3) + rr * 32;
        if (h >= H_) break;

        // ---- 31x31 depthwise conv, 7-wide rolling register window ----
        float accL[7];
        #pragma unroll
        for (int t = 0; t < 7; t++) accL[t] = 0.f;

        #pragma unroll 1
        for (int i = 0; i < KL; i++) {
            const float* xr = &tile[(h + i) * STR + col0];
            const float* wr = &wl[i * KL];
            float xw[7];
            #pragma unroll
            for (int t = 0; t < 7; t++) xw[t] = xr[t];
            #pragma unroll
            for (int j = 0; j < KL; j++) {
                const float wv = wr[j];
                #pragma unroll
                for (int t = 0; t < 7; t++)
                    accL[t] = fmaf(xw[(j + t) % 7], wv, accL[t]);
                if (j < KL - 1) xw[j % 7] = xr[j + 7];
            }
        }

        // ---- 5x5 depthwise conv (pad 2): located at +13 in the 15-halo tile ----
        float accS[7];
        #pragma unroll
        for (int t = 0; t < 7; t++) accS[t] = 0.f;
        #pragma unroll
        for (int i = 0; i < KS; i++) {
            const float* xr = &tile[(h + i + 13) * STR + col0 + 13];
            const float* wr = &ws[i * KS];
            float xv[11];
            #pragma unroll
            for (int t = 0; t < 11; t++) xv[t] = xr[t];
            #pragma unroll
            for (int j = 0; j < KS; j++) {
                const float wv = wr[j];
                #pragma unroll
                for (int t = 0; t < 7; t++)
                    accS[t] = fmaf(xv[j + t], wv, accS[t]);
            }
        }

        const size_t ob = (size_t)blk * HW_ + (size_t)h * W_ + col0;
        #pragma unroll
        for (int t = 0; t < 7; t++) {
            g_yl[ob + t] = accL[t];
            g_ys[ob + t] = accS[t];
            sL += accL[t]; qL = fmaf(accL[t], accL[t], qL);
            sS += accS[t]; qS = fmaf(accS[t], accS[t], qS);
        }
    }

    // ---- block reduction of the 4 stats ----
    #pragma unroll
    for (int o = 16; o; o >>= 1) {
        sL += __shfl_down_sync(0xffffffffu, sL, o);
        qL += __shfl_down_sync(0xffffffffu, qL, o);
        sS += __shfl_down_sync(0xffffffffu, sS, o);
        qS += __shfl_down_sync(0xffffffffu, qS, o);
    }
    const int lane = tid & 31, wp = tid >> 5;
    if (lane == 0) { red[wp*4+0]=sL; red[wp*4+1]=qL; red[wp*4+2]=sS; red[wp*4+3]=qS; }
    __syncthreads();
    if (tid < 4) {
        float v = 0.f;
        #pragma unroll
        for (int ww = 0; ww < 8; ww++) v += red[ww * 4 + tid];
        atomicAdd(&g_acc[c * 4 + tid], v);
    }
}

__global__ void k_stats(const float* __restrict__ gL, const float* __restrict__ bL,
                        const float* __restrict__ gS, const float* __restrict__ bS) {
    int c = blockIdx.x * blockDim.x + threadIdx.x;
    if (c >= C_) return;
    const float inv_n = 1.f / (float)NHW_;
    float mL = g_acc[c*4+0] * inv_n;
    float vL = g_acc[c*4+1] * inv_n - mL * mL;
    float aL = gL[c] * rsqrtf(vL + 1e-5f);
    float mS = g_acc[c*4+2] * inv_n;
    float vS = g_acc[c*4+3] * inv_n - mS * mS;
    float aS = gS[c] * rsqrtf(vS + 1e-5f);
    g_prm[c]        = aL;
    g_prm[C_ + c]   = aS;
    g_prm[2*C_ + c] = bL[c] - mL * aL + bS[c] - mS * aS;
}

__global__ __launch_bounds__(256) void k_out(float* __restrict__ out) {
    int i = blockIdx.x * blockDim.x + threadIdx.x;
    if (i >= TOT_ / 4) return;
    int e = i * 4;
    int c = (e / HW_) % C_;          // HW_ divisible by 4 -> channel constant in float4
    float aL = g_prm[c], aS = g_prm[C_ + c], bb = g_prm[2*C_ + c];
    float4 l = ((const float4*)g_yl)[i];
    float4 s = ((const float4*)g_ys)[i];
    float4 o;
    o.x = fmaf(aL, l.x, fmaf(aS, s.x, bb));
    o.y = fmaf(aL, l.y, fmaf(aS, s.y, bb));
    o.z = fmaf(aL, l.z, fmaf(aS, s.z, bb));
    o.w = fmaf(aL, l.w, fmaf(aS, s.w, bb));
    ((float4*)out)[i] = o;
}

extern "C" void kernel_launch(void* const* d_in, const int* in_sizes, int n_in,
                              void* d_out, int out_size) {
    const float* x  = (const float*)d_in[0];
    const float* wl = (const float*)d_in[1];
    const float* gl = (const float*)d_in[2];
    const float* bl = (const float*)d_in[3];
    const float* ws = (const float*)d_in[4];
    const float* gs = (const float*)d_in[5];
    const float* bs = (const float*)d_in[6];

    k_zero<<<6, 256>>>();
    k_conv<<<B_ * C_, 256>>>(x, wl, ws);
    k_stats<<<2, 192>>>(gl, bl, gs, bs);
    k_out<<<(TOT_ / 4 + 255) / 256, 256>>>((float*)d_out);
}